// round 7
// baseline (speedup 1.0000x reference)
#include <cuda_runtime.h>
#include <cstdint>

#define BB 4
#define SS 2048
#define DD 512
#define HH 8
#define DKK 64
#define MM (BB*SS)
#define NBH (BB*HH)

// Packed bf16x2 split planes (uint32 = 2 bf16 along last dim)
__device__ uint32_t g_Qh[NBH*SS*32], g_Ql[NBH*SS*32];   // [bh][s][d/2], pre-scaled by 1/8
__device__ uint32_t g_Kh[NBH*SS*32], g_Kl[NBH*SS*32];   // [bh][s][d/2]
__device__ uint32_t g_Vh[NBH*DKK*(SS/2)], g_Vl[NBH*DKK*(SS/2)]; // [bh][d][s/2]
__device__ float    g_C[BB*SS*DD];                      // context [B,S,D] fp32

// ---------------------------------------------------------------------------
__device__ __forceinline__ void mma_bf16(float* c, const uint32_t* a, const uint32_t* b) {
    asm volatile(
        "mma.sync.aligned.m16n8k16.row.col.f32.bf16.bf16.f32 "
        "{%0,%1,%2,%3}, {%4,%5,%6,%7}, {%8,%9}, {%0,%1,%2,%3};"
        : "+f"(c[0]), "+f"(c[1]), "+f"(c[2]), "+f"(c[3])
        : "r"(a[0]), "r"(a[1]), "r"(a[2]), "r"(a[3]), "r"(b[0]), "r"(b[1]));
}
__device__ __forceinline__ void pack_split(float x0, float x1, uint32_t& H, uint32_t& L) {
    uint32_t h;
    asm("cvt.rn.bf16x2.f32 %0, %1, %2;" : "=r"(h) : "f"(x1), "f"(x0));
    float h0 = __uint_as_float(h << 16);
    float h1 = __uint_as_float(h & 0xffff0000u);
    float r0 = x0 - h0, r1 = x1 - h1;
    uint32_t l;
    asm("cvt.rn.bf16x2.f32 %0, %1, %2;" : "=r"(l) : "f"(r1), "f"(r0));
    H = h; L = l;
}
__device__ __forceinline__ uint32_t smem_u32(const void* p) {
    uint32_t a;
    asm("{ .reg .u64 t; cvta.to.shared.u64 t, %1; cvt.u32.u64 %0, t; }" : "=r"(a) : "l"(p));
    return a;
}
__device__ __forceinline__ void cp16(uint32_t daddr, const void* gsrc) {
    asm volatile("cp.async.cg.shared.global [%0], [%1], 16;" :: "r"(daddr), "l"(gsrc));
}
#define CP_COMMIT() asm volatile("cp.async.commit_group;" ::: "memory")
#define CP_WAIT0()  asm volatile("cp.async.wait_group 0;" ::: "memory")
#define CP_WAIT1()  asm volatile("cp.async.wait_group 1;" ::: "memory")

// ---------------------------------------------------------------------------
// bf16-split GEMM (NT): C[m,n] = sum_k A[m,k]*W[n,k]   (R4-proven version)
// 128x128 tile, BK=32, 8 warps, warp tile 64x32, in-kernel split.
// which: 0=Q (pre-scaled 1/8), 1=K -> [bh][s][d/2]; 2=Vt -> [bh][d][s/2]; 3=fp32 out.
// ---------------------------------------------------------------------------
#define ST4 20   // smem row stride in uint32 (16 data + 4 pad)

__global__ __launch_bounds__(256)
void gemm_mma(const float* __restrict__ A_in, const float* __restrict__ W,
              float* __restrict__ out_direct, int which)
{
    __shared__ uint32_t Ahi[128*ST4], Alo[128*ST4], Bhi[128*ST4], Blo[128*ST4];

    const int tid = threadIdx.x;
    const int wid = tid >> 5;
    const int lid = tid & 31;
    const int gID = lid >> 2;
    const int tig = lid & 3;
    const int bm  = blockIdx.x * 128;
    const int bn  = blockIdx.y * 128;
    const int wm  = (wid & 1) * 64;
    const int wn  = (wid >> 1) * 32;

    const float* Ap = (which == 3) ? g_C : A_in;

    float acc[4][4][4];
    #pragma unroll
    for (int i = 0; i < 4; i++)
        #pragma unroll
        for (int j = 0; j < 4; j++)
            #pragma unroll
            for (int t = 0; t < 4; t++) acc[i][j][t] = 0.f;

    for (int c = 0; c < DD/32; c++) {
        const int k0 = c * 32;
        if (c) __syncthreads();
        #pragma unroll
        for (int q = 0; q < 4; q++) {
            int idx  = q * 256 + tid;
            int row  = idx >> 3;
            int j    = idx & 7;
            float4 a = *(const float4*)(Ap + (size_t)(bm + row) * DD + k0 + 4*j);
            float4 b = *(const float4*)(W  + (size_t)(bn + row) * DD + k0 + 4*j);
            uint32_t h0,l0,h1,l1;
            pack_split(a.x, a.y, h0, l0); pack_split(a.z, a.w, h1, l1);
            int off = row * ST4 + 2*j;
            *(uint2*)&Ahi[off] = make_uint2(h0, h1);
            *(uint2*)&Alo[off] = make_uint2(l0, l1);
            pack_split(b.x, b.y, h0, l0); pack_split(b.z, b.w, h1, l1);
            *(uint2*)&Bhi[off] = make_uint2(h0, h1);
            *(uint2*)&Blo[off] = make_uint2(l0, l1);
        }
        __syncthreads();

        #pragma unroll
        for (int ks = 0; ks < 2; ks++) {
            const int kp = 8*ks + tig;
            uint32_t bhf[4][2], blf[4][2];
            #pragma unroll
            for (int ni = 0; ni < 4; ni++) {
                int n = wn + ni*8 + gID;
                bhf[ni][0] = Bhi[n*ST4 + kp];  bhf[ni][1] = Bhi[n*ST4 + kp + 4];
                blf[ni][0] = Blo[n*ST4 + kp];  blf[ni][1] = Blo[n*ST4 + kp + 4];
            }
            #pragma unroll
            for (int mi = 0; mi < 4; mi++) {
                int m = wm + mi*16 + gID;
                uint32_t ahf[4], alf[4];
                ahf[0] = Ahi[m*ST4 + kp];       ahf[1] = Ahi[(m+8)*ST4 + kp];
                ahf[2] = Ahi[m*ST4 + kp + 4];   ahf[3] = Ahi[(m+8)*ST4 + kp + 4];
                alf[0] = Alo[m*ST4 + kp];       alf[1] = Alo[(m+8)*ST4 + kp];
                alf[2] = Alo[m*ST4 + kp + 4];   alf[3] = Alo[(m+8)*ST4 + kp + 4];
                #pragma unroll
                for (int ni = 0; ni < 4; ni++) {
                    mma_bf16(acc[mi][ni], ahf, bhf[ni]);
                    mma_bf16(acc[mi][ni], ahf, blf[ni]);
                    mma_bf16(acc[mi][ni], alf, bhf[ni]);
                }
            }
        }
    }

    // ---- epilogue ----
    const float qscale = (which == 0) ? 0.125f : 1.0f;   // fold 1/sqrt(dk) into Q (exact pow2)
    #pragma unroll
    for (int mi = 0; mi < 4; mi++) {
        int rm = bm + wm + mi*16 + gID;
        #pragma unroll
        for (int ni = 0; ni < 4; ni++) {
            int n = bn + wn + ni*8 + 2*tig;
            float* a = acc[mi][ni];
            if (which <= 1) {
                uint32_t* Hp = (which == 0) ? g_Qh : g_Kh;
                uint32_t* Lp = (which == 0) ? g_Ql : g_Kl;
                int h = n >> 6, dp = (n & 63) >> 1;
                uint32_t H, L;
                pack_split(a[0]*qscale, a[1]*qscale, H, L);
                size_t o0 = ((size_t)((rm >> 11)*HH + h)*SS + (rm & (SS-1)))*32 + dp;
                Hp[o0] = H; Lp[o0] = L;
                pack_split(a[2]*qscale, a[3]*qscale, H, L);
                int r1 = rm + 8;
                size_t o1 = ((size_t)((r1 >> 11)*HH + h)*SS + (r1 & (SS-1)))*32 + dp;
                Hp[o1] = H; Lp[o1] = L;
            } else if (which == 2) {
                int h = rm >> 6, dj = rm & 63;
                int b = n >> 11, sl = n & (SS-1);
                uint32_t H, L;
                pack_split(a[0], a[1], H, L);
                size_t o0 = ((size_t)(b*HH + h)*DKK + dj)*(SS/2) + (sl >> 1);
                g_Vh[o0] = H; g_Vl[o0] = L;
                pack_split(a[2], a[3], H, L);
                size_t o1 = ((size_t)(b*HH + h)*DKK + dj + 8)*(SS/2) + (sl >> 1);
                g_Vh[o1] = H; g_Vl[o1] = L;
            } else {
                *(float2*)&out_direct[(size_t)rm*DD + n]     = make_float2(a[0], a[1]);
                *(float2*)&out_direct[(size_t)(rm+8)*DD + n] = make_float2(a[2], a[3]);
            }
        }
    }
}

// ---------------------------------------------------------------------------
// bf16-split flash attention (causal). 64 q-rows/block, 4 warps (16 rows each).
// ONLY delta vs R4: K/V tile staging is cp.async double-buffered.
// ---------------------------------------------------------------------------
#define AST 36              // smem row stride in u32
#define APL (64*AST)        // u32 per plane
#define ASMEM (2*4*APL*4)   // 73728 B

__global__ __launch_bounds__(128, 3)
void attn_mma()
{
    extern __shared__ uint32_t smA[];
    const uint32_t sb = smem_u32(smA);

    const int tid = threadIdx.x;
    const int w   = tid >> 5;
    const int lid = tid & 31;
    const int gID = lid >> 2;
    const int tig = lid & 3;

    const int qt = (int)gridDim.x - 1 - (int)blockIdx.x;  // long blocks first
    const int bh = blockIdx.y;

    const int q0l = w*16 + gID;            // 0..63 (+8 second row)
    const int q0  = qt*64 + q0l;

    auto stage_load = [&](int st, int kt) {
        #pragma unroll
        for (int q = 0; q < 16; q++) {
            int idx = q * 128 + tid;       // 0..2047
            int pl  = idx >> 9;            // plane 0..3
            int rem = idx & 511;
            int row = rem >> 3;            // 0..63
            int j   = (rem & 7) << 2;      // 0..28
            const uint32_t* src;
            if (pl == 0)      src = g_Kh + ((size_t)bh*SS + kt*64 + row)*32 + j;
            else if (pl == 1) src = g_Kl + ((size_t)bh*SS + kt*64 + row)*32 + j;
            else if (pl == 2) src = g_Vh + ((size_t)bh*DKK + row)*(SS/2) + kt*32 + j;
            else              src = g_Vl + ((size_t)bh*DKK + row)*(SS/2) + kt*32 + j;
            cp16(sb + ((st*4 + pl) * APL + row * AST + j) * 4, src);
        }
        CP_COMMIT();
    };

    // ---- Q fragments (hi/lo, pre-scaled by 1/8), resident all block ----
    uint32_t qh[4][4], ql[4][4];
    {
        const uint32_t* Qhp = g_Qh + ((size_t)bh*SS + q0)*32;
        const uint32_t* Qlp = g_Ql + ((size_t)bh*SS + q0)*32;
        #pragma unroll
        for (int ks = 0; ks < 4; ks++) {
            int p = 8*ks + tig;
            qh[ks][0] = Qhp[p];      qh[ks][1] = Qhp[8*32 + p];
            qh[ks][2] = Qhp[p + 4];  qh[ks][3] = Qhp[8*32 + p + 4];
            ql[ks][0] = Qlp[p];      ql[ks][1] = Qlp[8*32 + p];
            ql[ks][2] = Qlp[p + 4];  ql[ks][3] = Qlp[8*32 + p + 4];
        }
    }

    float m0 = -1e30f, m1 = -1e30f, l0 = 0.f, l1 = 0.f;
    float accO[8][4];
    #pragma unroll
    for (int nt = 0; nt < 8; nt++)
        #pragma unroll
        for (int t = 0; t < 4; t++) accO[nt][t] = 0.f;

    const int ntile = qt + 1;
    stage_load(0, 0);

    for (int kt = 0; kt < ntile; kt++) {
        const int cur = kt & 1;
        if (kt + 1 < ntile) { stage_load(cur ^ 1, kt + 1); CP_WAIT1(); }
        else                { CP_WAIT0(); }
        __syncthreads();

        const uint32_t* sKh = smA + (cur*4 + 0) * APL;
        const uint32_t* sKl = smA + (cur*4 + 1) * APL;
        const uint32_t* sVh = smA + (cur*4 + 2) * APL;
        const uint32_t* sVl = smA + (cur*4 + 3) * APL;

        // ---- S = Q K^T (3-term split; Q pre-scaled) ----
        float accS[8][4];
        #pragma unroll
        for (int nt = 0; nt < 8; nt++)
            #pragma unroll
            for (int t = 0; t < 4; t++) accS[nt][t] = 0.f;

        #pragma unroll
        for (int ks = 0; ks < 4; ks++) {
            const int kp = 8*ks + tig;
            #pragma unroll
            for (int nt = 0; nt < 8; nt++) {
                int row = (nt*8 + gID) * AST;
                uint32_t bh_[2] = { sKh[row + kp], sKh[row + kp + 4] };
                uint32_t bl_[2] = { sKl[row + kp], sKl[row + kp + 4] };
                mma_bf16(accS[nt], qh[ks], bh_);
                mma_bf16(accS[nt], qh[ks], bl_);
                mma_bf16(accS[nt], ql[ks], bh_);
            }
        }

        // ---- causal mask (diagonal tile only) ----
        if (kt == qt) {
            #pragma unroll
            for (int nt = 0; nt < 8; nt++) {
                int c0 = nt*8 + 2*tig;
                if (c0     > q0l)     accS[nt][0] = -1e30f;
                if (c0 + 1 > q0l)     accS[nt][1] = -1e30f;
                if (c0     > q0l + 8) accS[nt][2] = -1e30f;
                if (c0 + 1 > q0l + 8) accS[nt][3] = -1e30f;
            }
        }

        // ---- online softmax ----
        float mx0 = -1e30f, mx1 = -1e30f;
        #pragma unroll
        for (int nt = 0; nt < 8; nt++) {
            mx0 = fmaxf(mx0, fmaxf(accS[nt][0], accS[nt][1]));
            mx1 = fmaxf(mx1, fmaxf(accS[nt][2], accS[nt][3]));
        }
        #pragma unroll
        for (int off = 1; off <= 2; off <<= 1) {
            mx0 = fmaxf(mx0, __shfl_xor_sync(0xffffffffu, mx0, off));
            mx1 = fmaxf(mx1, __shfl_xor_sync(0xffffffffu, mx1, off));
        }
        float mn0 = fmaxf(m0, mx0), mn1 = fmaxf(m1, mx1);
        float corr0 = __expf(m0 - mn0), corr1 = __expf(m1 - mn1);
        m0 = mn0; m1 = mn1;

        float sum0 = 0.f, sum1 = 0.f;
        #pragma unroll
        for (int nt = 0; nt < 8; nt++) {
            accS[nt][0] = __expf(accS[nt][0] - mn0);
            accS[nt][1] = __expf(accS[nt][1] - mn0);
            accS[nt][2] = __expf(accS[nt][2] - mn1);
            accS[nt][3] = __expf(accS[nt][3] - mn1);
            sum0 += accS[nt][0] + accS[nt][1];
            sum1 += accS[nt][2] + accS[nt][3];
        }
        #pragma unroll
        for (int off = 1; off <= 2; off <<= 1) {
            sum0 += __shfl_xor_sync(0xffffffffu, sum0, off);
            sum1 += __shfl_xor_sync(0xffffffffu, sum1, off);
        }
        l0 = l0*corr0 + sum0;
        l1 = l1*corr1 + sum1;
        #pragma unroll
        for (int nt = 0; nt < 8; nt++) {
            accO[nt][0] *= corr0; accO[nt][1] *= corr0;
            accO[nt][2] *= corr1; accO[nt][3] *= corr1;
        }

        // ---- P -> bf16 split A-fragments ----
        uint32_t ph[4][4], pl_[4][4];
        #pragma unroll
        for (int ks = 0; ks < 4; ks++) {
            pack_split(accS[2*ks  ][0], accS[2*ks  ][1], ph[ks][0], pl_[ks][0]);
            pack_split(accS[2*ks  ][2], accS[2*ks  ][3], ph[ks][1], pl_[ks][1]);
            pack_split(accS[2*ks+1][0], accS[2*ks+1][1], ph[ks][2], pl_[ks][2]);
            pack_split(accS[2*ks+1][2], accS[2*ks+1][3], ph[ks][3], pl_[ks][3]);
        }

        // ---- O += P V (3-term split) ----
        #pragma unroll
        for (int ks = 0; ks < 4; ks++) {
            const int kp = 8*ks + tig;
            #pragma unroll
            for (int nt = 0; nt < 8; nt++) {
                int row = (nt*8 + gID) * AST;
                uint32_t bh_[2] = { sVh[row + kp], sVh[row + kp + 4] };
                uint32_t bl_[2] = { sVl[row + kp], sVl[row + kp + 4] };
                mma_bf16(accO[nt], ph[ks], bh_);
                mma_bf16(accO[nt], ph[ks], bl_);
                mma_bf16(accO[nt], pl_[ks], bh_);
            }
        }
        __syncthreads();
    }

    // ---- epilogue: context[b][s][h*64+d] fp32 ----
    const int b = bh >> 3, h = bh & 7;
    const float inv0 = 1.f / l0, inv1 = 1.f / l1;
    #pragma unroll
    for (int nt = 0; nt < 8; nt++) {
        int d = h*64 + nt*8 + 2*tig;
        *(float2*)&g_C[((size_t)b*SS + q0)*DD + d] =
            make_float2(accO[nt][0]*inv0, accO[nt][1]*inv0);
        *(float2*)&g_C[((size_t)b*SS + q0 + 8)*DD + d] =
            make_float2(accO[nt][2]*inv1, accO[nt][3]*inv1);
    }
}

// ---------------------------------------------------------------------------
extern "C" void kernel_launch(void* const* d_in, const int* in_sizes, int n_in,
                              void* d_out, int out_size)
{
    const float* Xq = (const float*)d_in[0];
    const float* Xk = (const float*)d_in[1];
    const float* Xv = (const float*)d_in[2];
    const float* Wq = (const float*)d_in[3];
    const float* Wk = (const float*)d_in[4];
    const float* Wv = (const float*)d_in[5];
    const float* Wo = (const float*)d_in[6];
    float* out = (float*)d_out;

    static bool attr_done = false;
    if (!attr_done) {
        cudaFuncSetAttribute(attn_mma, cudaFuncAttributeMaxDynamicSharedMemorySize, ASMEM);
        attr_done = true;
    }

    dim3 gqk(MM/128, DD/128);     // 64 x 4
    gemm_mma<<<gqk, 256>>>(Xq, Wq, nullptr, 0);
    gemm_mma<<<gqk, 256>>>(Xk, Wk, nullptr, 1);
    gemm_mma<<<dim3(DD/128, MM/128), 256>>>(Wv, Xv, nullptr, 2);   // Vt = Wv @ Xv^T

    attn_mma<<<dim3(SS/64, NBH), 128, ASMEM>>>();                  // 32 x 32

    gemm_mma<<<gqk, 256>>>(nullptr, Wo, out, 3);
}

// round 8
// speedup vs baseline: 1.2126x; 1.2126x over previous
#include <cuda_runtime.h>
#include <cstdint>

#define BB 4
#define SS 2048
#define DD 512
#define HH 8
#define DKK 64
#define MM (BB*SS)
#define NBH (BB*HH)

// Packed bf16x2 split planes (uint32 = 2 bf16 along last dim)
__device__ uint32_t g_Qh[NBH*SS*32], g_Ql[NBH*SS*32];   // [bh][s][d/2], pre-scaled by 1/8
__device__ uint32_t g_Kh[NBH*SS*32], g_Kl[NBH*SS*32];   // [bh][s][d/2]
__device__ uint32_t g_Vh[NBH*DKK*(SS/2)], g_Vl[NBH*DKK*(SS/2)]; // [bh][d][s/2] (transposed)
__device__ float    g_C[BB*SS*DD];                      // context [B,S,D] fp32

// ---------------------------------------------------------------------------
__device__ __forceinline__ void mma_bf16(float* c, const uint32_t* a, const uint32_t* b) {
    asm volatile(
        "mma.sync.aligned.m16n8k16.row.col.f32.bf16.bf16.f32 "
        "{%0,%1,%2,%3}, {%4,%5,%6,%7}, {%8,%9}, {%0,%1,%2,%3};"
        : "+f"(c[0]), "+f"(c[1]), "+f"(c[2]), "+f"(c[3])
        : "r"(a[0]), "r"(a[1]), "r"(a[2]), "r"(a[3]), "r"(b[0]), "r"(b[1]));
}
__device__ __forceinline__ void pack_split(float x0, float x1, uint32_t& H, uint32_t& L) {
    uint32_t h;
    asm("cvt.rn.bf16x2.f32 %0, %1, %2;" : "=r"(h) : "f"(x1), "f"(x0));
    float h0 = __uint_as_float(h << 16);
    float h1 = __uint_as_float(h & 0xffff0000u);
    float r0 = x0 - h0, r1 = x1 - h1;
    uint32_t l;
    asm("cvt.rn.bf16x2.f32 %0, %1, %2;" : "=r"(l) : "f"(r1), "f"(r0));
    H = h; L = l;
}

// ---------------------------------------------------------------------------
// bf16-split GEMM (NT): C[m,n] = sum_k A[m,k]*W[n,k]   (R4 base + reg prefetch)
// 128x128 tile, BK=32, 8 warps, warp tile 64x32, in-kernel split.
// which: 0=Q (pre-scaled 1/8), 1=K -> [bh][s][d/2]; 2=Vt -> [bh][d][s/2]; 3=fp32 out.
// ---------------------------------------------------------------------------
#define ST4 20   // smem row stride in uint32 (16 data + 4 pad)

__global__ __launch_bounds__(256)
void gemm_mma(const float* __restrict__ A_in, const float* __restrict__ W,
              float* __restrict__ out_direct, int which)
{
    __shared__ uint32_t Ahi[128*ST4], Alo[128*ST4], Bhi[128*ST4], Blo[128*ST4];

    const int tid = threadIdx.x;
    const int wid = tid >> 5;
    const int lid = tid & 31;
    const int gID = lid >> 2;
    const int tig = lid & 3;
    const int bm  = blockIdx.x * 128;
    const int bn  = blockIdx.y * 128;
    const int wm  = (wid & 1) * 64;
    const int wn  = (wid >> 1) * 32;

    const float* Ap = (which == 3) ? g_C : A_in;

    // per-thread gmem addresses (row/j fixed per q slot)
    const int row_[4] = { (0*256+tid)>>3, (1*256+tid)>>3, (2*256+tid)>>3, (3*256+tid)>>3 };
    const int j_[4]   = { (0*256+tid)&7,  (1*256+tid)&7,  (2*256+tid)&7,  (3*256+tid)&7  };

    float acc[4][4][4];
    #pragma unroll
    for (int i = 0; i < 4; i++)
        #pragma unroll
        for (int j = 0; j < 4; j++)
            #pragma unroll
            for (int t = 0; t < 4; t++) acc[i][j][t] = 0.f;

    // prefetch chunk 0 into registers
    float4 pa[4], pb[4];
    #pragma unroll
    for (int q = 0; q < 4; q++) {
        pa[q] = *(const float4*)(Ap + (size_t)(bm + row_[q]) * DD + 4*j_[q]);
        pb[q] = *(const float4*)(W  + (size_t)(bn + row_[q]) * DD + 4*j_[q]);
    }

    for (int c = 0; c < DD/32; c++) {
        if (c) __syncthreads();   // previous chunk's MMA readers done
        // ---- split prefetched regs -> smem ----
        #pragma unroll
        for (int q = 0; q < 4; q++) {
            uint32_t h0,l0,h1,l1;
            pack_split(pa[q].x, pa[q].y, h0, l0); pack_split(pa[q].z, pa[q].w, h1, l1);
            int off = row_[q] * ST4 + 2*j_[q];
            *(uint2*)&Ahi[off] = make_uint2(h0, h1);
            *(uint2*)&Alo[off] = make_uint2(l0, l1);
            pack_split(pb[q].x, pb[q].y, h0, l0); pack_split(pb[q].z, pb[q].w, h1, l1);
            *(uint2*)&Bhi[off] = make_uint2(h0, h1);
            *(uint2*)&Blo[off] = make_uint2(l0, l1);
        }
        __syncthreads();

        // ---- issue next chunk's LDGs (latency overlapped by MMAs below) ----
        if (c + 1 < DD/32) {
            const int k1 = (c + 1) * 32;
            #pragma unroll
            for (int q = 0; q < 4; q++) {
                pa[q] = *(const float4*)(Ap + (size_t)(bm + row_[q]) * DD + k1 + 4*j_[q]);
                pb[q] = *(const float4*)(W  + (size_t)(bn + row_[q]) * DD + k1 + 4*j_[q]);
            }
        }

        // ---- 2 k-steps of 16 ----
        #pragma unroll
        for (int ks = 0; ks < 2; ks++) {
            const int kp = 8*ks + tig;
            uint32_t bhf[4][2], blf[4][2];
            #pragma unroll
            for (int ni = 0; ni < 4; ni++) {
                int n = wn + ni*8 + gID;
                bhf[ni][0] = Bhi[n*ST4 + kp];  bhf[ni][1] = Bhi[n*ST4 + kp + 4];
                blf[ni][0] = Blo[n*ST4 + kp];  blf[ni][1] = Blo[n*ST4 + kp + 4];
            }
            #pragma unroll
            for (int mi = 0; mi < 4; mi++) {
                int m = wm + mi*16 + gID;
                uint32_t ahf[4], alf[4];
                ahf[0] = Ahi[m*ST4 + kp];       ahf[1] = Ahi[(m+8)*ST4 + kp];
                ahf[2] = Ahi[m*ST4 + kp + 4];   ahf[3] = Ahi[(m+8)*ST4 + kp + 4];
                alf[0] = Alo[m*ST4 + kp];       alf[1] = Alo[(m+8)*ST4 + kp];
                alf[2] = Alo[m*ST4 + kp + 4];   alf[3] = Alo[(m+8)*ST4 + kp + 4];
                #pragma unroll
                for (int ni = 0; ni < 4; ni++) {
                    mma_bf16(acc[mi][ni], ahf, bhf[ni]);
                    mma_bf16(acc[mi][ni], ahf, blf[ni]);
                    mma_bf16(acc[mi][ni], alf, bhf[ni]);
                }
            }
        }
    }

    // ---- epilogue ----
    const float qscale = (which == 0) ? 0.125f : 1.0f;   // fold 1/sqrt(dk) into Q (exact pow2)
    #pragma unroll
    for (int mi = 0; mi < 4; mi++) {
        int rm = bm + wm + mi*16 + gID;
        #pragma unroll
        for (int ni = 0; ni < 4; ni++) {
            int n = bn + wn + ni*8 + 2*tig;
            float* a = acc[mi][ni];
            if (which <= 1) {
                uint32_t* Hp = (which == 0) ? g_Qh : g_Kh;
                uint32_t* Lp = (which == 0) ? g_Ql : g_Kl;
                int h = n >> 6, dp = (n & 63) >> 1;
                uint32_t H, L;
                pack_split(a[0]*qscale, a[1]*qscale, H, L);
                size_t o0 = ((size_t)((rm >> 11)*HH + h)*SS + (rm & (SS-1)))*32 + dp;
                Hp[o0] = H; Lp[o0] = L;
                pack_split(a[2]*qscale, a[3]*qscale, H, L);
                int r1 = rm + 8;
                size_t o1 = ((size_t)((r1 >> 11)*HH + h)*SS + (r1 & (SS-1)))*32 + dp;
                Hp[o1] = H; Lp[o1] = L;
            } else if (which == 2) {
                int h = rm >> 6, dj = rm & 63;
                int b = n >> 11, sl = n & (SS-1);
                uint32_t H, L;
                pack_split(a[0], a[1], H, L);
                size_t o0 = ((size_t)(b*HH + h)*DKK + dj)*(SS/2) + (sl >> 1);
                g_Vh[o0] = H; g_Vl[o0] = L;
                pack_split(a[2], a[3], H, L);
                size_t o1 = ((size_t)(b*HH + h)*DKK + dj + 8)*(SS/2) + (sl >> 1);
                g_Vh[o1] = H; g_Vl[o1] = L;
            } else {
                *(float2*)&out_direct[(size_t)rm*DD + n]     = make_float2(a[0], a[1]);
                *(float2*)&out_direct[(size_t)(rm+8)*DD + n] = make_float2(a[2], a[3]);
            }
        }
    }
}

// ---------------------------------------------------------------------------
// bf16-split flash attention (causal) — R4-exact structure (static smem,
// synchronous staging, 4 warps / 64 q-rows).  Only delta: Q pre-scaled, so the
// per-tile scale pass is gone.
// ---------------------------------------------------------------------------
#define AST 36   // attn smem row stride in uint32 (32 data + 4 pad)

__global__ __launch_bounds__(128)
void attn_mma()
{
    __shared__ uint32_t sKh[64*AST], sKl[64*AST], sVh[64*AST], sVl[64*AST];

    const int tid = threadIdx.x;
    const int w   = tid >> 5;
    const int lid = tid & 31;
    const int gID = lid >> 2;
    const int tig = lid & 3;

    const int qt = (int)gridDim.x - 1 - (int)blockIdx.x;  // long rows first
    const int bh = blockIdx.y;

    const int q0l = w*16 + gID;          // local row (0..63), second row +8
    const int q0  = qt*64 + q0l;

    // ---- Q fragments (hi/lo, pre-scaled), resident for the whole block ----
    uint32_t qh[4][4], ql[4][4];
    {
        const uint32_t* Qhp = g_Qh + ((size_t)bh*SS + q0)*32;
        const uint32_t* Qlp = g_Ql + ((size_t)bh*SS + q0)*32;
        #pragma unroll
        for (int ks = 0; ks < 4; ks++) {
            int p = 8*ks + tig;
            qh[ks][0] = Qhp[p];          qh[ks][1] = Qhp[8*32 + p];
            qh[ks][2] = Qhp[p + 4];      qh[ks][3] = Qhp[8*32 + p + 4];
            ql[ks][0] = Qlp[p];          ql[ks][1] = Qlp[8*32 + p];
            ql[ks][2] = Qlp[p + 4];      ql[ks][3] = Qlp[8*32 + p + 4];
        }
    }

    float m0 = -1e30f, m1 = -1e30f, l0 = 0.f, l1 = 0.f;
    float accO[8][4];
    #pragma unroll
    for (int nt = 0; nt < 8; nt++)
        #pragma unroll
        for (int t = 0; t < 4; t++) accO[nt][t] = 0.f;

    for (int kt = 0; kt <= qt; kt++) {
        __syncthreads();   // previous tile's readers done
        // ---- load K ([s][d/2]) and Vt ([d][s/2]) hi/lo tiles ----
        #pragma unroll
        for (int it = 0; it < 4; it++) {
            int idx = it*128 + tid;
            int r   = idx >> 3;
            int c4  = (idx & 7) << 2;
            size_t ko = ((size_t)bh*SS + kt*64 + r)*32 + c4;
            *(int4*)&sKh[r*AST + c4] = *(const int4*)&g_Kh[ko];
            *(int4*)&sKl[r*AST + c4] = *(const int4*)&g_Kl[ko];
            size_t vo = ((size_t)bh*DKK + r)*(SS/2) + kt*32 + c4;
            *(int4*)&sVh[r*AST + c4] = *(const int4*)&g_Vh[vo];
            *(int4*)&sVl[r*AST + c4] = *(const int4*)&g_Vl[vo];
        }
        __syncthreads();

        // ---- S = Q K^T (3-term split; Q pre-scaled) ----
        float accS[8][4];
        #pragma unroll
        for (int nt = 0; nt < 8; nt++)
            #pragma unroll
            for (int t = 0; t < 4; t++) accS[nt][t] = 0.f;

        #pragma unroll
        for (int ks = 0; ks < 4; ks++) {
            const int kp = 8*ks + tig;
            #pragma unroll
            for (int nt = 0; nt < 8; nt++) {
                int row = (nt*8 + gID) * AST;
                uint32_t bh_[2] = { sKh[row + kp], sKh[row + kp + 4] };
                uint32_t bl_[2] = { sKl[row + kp], sKl[row + kp + 4] };
                mma_bf16(accS[nt], qh[ks], bh_);
                mma_bf16(accS[nt], qh[ks], bl_);
                mma_bf16(accS[nt], ql[ks], bh_);
            }
        }

        // ---- causal mask (diagonal tile only) ----
        if (kt == qt) {
            #pragma unroll
            for (int nt = 0; nt < 8; nt++) {
                int c0 = nt*8 + 2*tig;
                if (c0     > q0l)     accS[nt][0] = -1e30f;
                if (c0 + 1 > q0l)     accS[nt][1] = -1e30f;
                if (c0     > q0l + 8) accS[nt][2] = -1e30f;
                if (c0 + 1 > q0l + 8) accS[nt][3] = -1e30f;
            }
        }

        // ---- online softmax ----
        float mx0 = -1e30f, mx1 = -1e30f;
        #pragma unroll
        for (int nt = 0; nt < 8; nt++) {
            mx0 = fmaxf(mx0, fmaxf(accS[nt][0], accS[nt][1]));
            mx1 = fmaxf(mx1, fmaxf(accS[nt][2], accS[nt][3]));
        }
        #pragma unroll
        for (int off = 1; off <= 2; off <<= 1) {
            mx0 = fmaxf(mx0, __shfl_xor_sync(0xffffffffu, mx0, off));
            mx1 = fmaxf(mx1, __shfl_xor_sync(0xffffffffu, mx1, off));
        }
        float mn0 = fmaxf(m0, mx0), mn1 = fmaxf(m1, mx1);
        float corr0 = __expf(m0 - mn0), corr1 = __expf(m1 - mn1);
        m0 = mn0; m1 = mn1;

        float sum0 = 0.f, sum1 = 0.f;
        #pragma unroll
        for (int nt = 0; nt < 8; nt++) {
            accS[nt][0] = __expf(accS[nt][0] - mn0);
            accS[nt][1] = __expf(accS[nt][1] - mn0);
            accS[nt][2] = __expf(accS[nt][2] - mn1);
            accS[nt][3] = __expf(accS[nt][3] - mn1);
            sum0 += accS[nt][0] + accS[nt][1];
            sum1 += accS[nt][2] + accS[nt][3];
        }
        #pragma unroll
        for (int off = 1; off <= 2; off <<= 1) {
            sum0 += __shfl_xor_sync(0xffffffffu, sum0, off);
            sum1 += __shfl_xor_sync(0xffffffffu, sum1, off);
        }
        l0 = l0*corr0 + sum0;
        l1 = l1*corr1 + sum1;
        #pragma unroll
        for (int nt = 0; nt < 8; nt++) {
            accO[nt][0] *= corr0; accO[nt][1] *= corr0;
            accO[nt][2] *= corr1; accO[nt][3] *= corr1;
        }

        // ---- P -> bf16 split A-fragments (register-only remap) ----
        uint32_t ph[4][4], pl_[4][4];
        #pragma unroll
        for (int ks = 0; ks < 4; ks++) {
            pack_split(accS[2*ks  ][0], accS[2*ks  ][1], ph[ks][0], pl_[ks][0]);
            pack_split(accS[2*ks  ][2], accS[2*ks  ][3], ph[ks][1], pl_[ks][1]);
            pack_split(accS[2*ks+1][0], accS[2*ks+1][1], ph[ks][2], pl_[ks][2]);
            pack_split(accS[2*ks+1][2], accS[2*ks+1][3], ph[ks][3], pl_[ks][3]);
        }

        // ---- O += P V (3-term split) ----
        #pragma unroll
        for (int ks = 0; ks < 4; ks++) {
            const int kp = 8*ks + tig;
            #pragma unroll
            for (int nt = 0; nt < 8; nt++) {
                int row = (nt*8 + gID) * AST;
                uint32_t bh_[2] = { sVh[row + kp], sVh[row + kp + 4] };
                uint32_t bl_[2] = { sVl[row + kp], sVl[row + kp + 4] };
                mma_bf16(accO[nt], ph[ks], bh_);
                mma_bf16(accO[nt], ph[ks], bl_);
                mma_bf16(accO[nt], pl_[ks], bh_);
            }
        }
    }

    // ---- epilogue: context[b][s][h*64+d] fp32 ----
    const int b = bh >> 3, h = bh & 7;
    const float inv0 = 1.f / l0, inv1 = 1.f / l1;
    #pragma unroll
    for (int nt = 0; nt < 8; nt++) {
        int d = h*64 + nt*8 + 2*tig;
        *(float2*)&g_C[((size_t)b*SS + q0)*DD + d] =
            make_float2(accO[nt][0]*inv0, accO[nt][1]*inv0);
        *(float2*)&g_C[((size_t)b*SS + q0 + 8)*DD + d] =
            make_float2(accO[nt][2]*inv1, accO[nt][3]*inv1);
    }
}

// ---------------------------------------------------------------------------
extern "C" void kernel_launch(void* const* d_in, const int* in_sizes, int n_in,
                              void* d_out, int out_size)
{
    const float* Xq = (const float*)d_in[0];
    const float* Xk = (const float*)d_in[1];
    const float* Xv = (const float*)d_in[2];
    const float* Wq = (const float*)d_in[3];
    const float* Wk = (const float*)d_in[4];
    const float* Wv = (const float*)d_in[5];
    const float* Wo = (const float*)d_in[6];
    float* out = (float*)d_out;

    dim3 gqk(MM/128, DD/128);     // 64 x 4
    gemm_mma<<<gqk, 256>>>(Xq, Wq, nullptr, 0);
    gemm_mma<<<gqk, 256>>>(Xk, Wk, nullptr, 1);
    gemm_mma<<<dim3(DD/128, MM/128), 256>>>(Wv, Xv, nullptr, 2);   // Vt = Wv @ Xv^T

    attn_mma<<<dim3(SS/64, NBH), 128>>>();                         // 32 x 32

    gemm_mma<<<gqk, 256>>>(nullptr, Wo, out, 3);
}